// round 14
// baseline (speedup 1.0000x reference)
#include <cuda_runtime.h>
#include <cuda_fp16.h>
#include <cstdint>

#define N_FEAT 32
#define MAX_NODES 524288
#define MAX_EDGES 4194304
#define TN 128

#define XH_STRIDE 40
#define WH_STRIDE 136
#define ST_STRIDE 136

// Scratch. xt REL-MAJOR: xt[rel][node][32] fp16 (4 x 32 MB).
__device__ __half g_xt[(size_t)4 * MAX_NODES * N_FEAT];
__device__ __half g_agg1[(size_t)MAX_NODES * N_FEAT];
__device__ __half g_agg2[(size_t)MAX_NODES * N_FEAT];
__device__ uint2  g_esd[MAX_EDGES];          // (src,dst) binned by rel
__device__ int g_cnt4[4];
__device__ int g_off[5];
__device__ int g_cursor[4];
__device__ unsigned int g_done;

// ---------------------------------------------------------------------------
// Zero counters (must precede tf<0>'s fused histogram).
// ---------------------------------------------------------------------------
__global__ void zc_k()
{
    if (threadIdx.x < 4) g_cnt4[threadIdx.x] = 0;
    if (threadIdx.x == 4) g_done = 0u;
}

// ---------------------------------------------------------------------------
// Reorder into rel bins; warp-aggregated ranking, block-aggregated cursors.
// (offsets/cursors were produced by tf<0>'s fused histogram tail)
// ---------------------------------------------------------------------------
__global__ void __launch_bounds__(256) reorder_k(
    const int* __restrict__ src, const int* __restrict__ dst,
    const int* __restrict__ et, uint2* __restrict__ esd, int ne)
{
    __shared__ int h[4];
    __shared__ int base[4];
    if (threadIdx.x < 4) h[threadIdx.x] = 0;
    __syncthreads();

    const int e = blockIdx.x * 256 + threadIdx.x;
    int r = 0, pos_local = 0;
    uint2 sd = make_uint2(0u, 0u);
    const bool valid = (e < ne);
    if (valid) {
        r = __ldg(et + e);
        sd.x = (unsigned int)__ldg(src + e);
        sd.y = (unsigned int)__ldg(dst + e);
        const unsigned int mask = __match_any_sync(__activemask(), r);
        const unsigned int lt   = (1u << (threadIdx.x & 31)) - 1u;
        const int rank = __popc(mask & lt);
        int wbase = 0;
        if (rank == 0) wbase = atomicAdd(&h[r], __popc(mask));
        const int leader = __ffs(mask) - 1;
        wbase = __shfl_sync(0xffffffffu, wbase, leader);
        pos_local = wbase + rank;
    }
    __syncthreads();
    if (threadIdx.x < 4)
        base[threadIdx.x] = atomicAdd(&g_cursor[threadIdx.x], h[threadIdx.x]);
    __syncthreads();
    if (valid) esd[base[r] + pos_local] = sd;
}

// ---------------------------------------------------------------------------
// Binned scatter, grid-stride persistent: 4 edges/thread/iter, 4 lanes/edge.
// Loop keeps occupancy flat and overlaps next iteration's loads with the
// in-flight (no-return) REDs.
// ---------------------------------------------------------------------------
__global__ void __launch_bounds__(256) scatter_k(
    const __half* __restrict__ xt, const uint2* __restrict__ esd,
    __half* __restrict__ agg, int ne, int nnodes)
{
    const int o1 = __ldg(&g_off[1]), o2 = __ldg(&g_off[2]), o3 = __ldg(&g_off[3]);
    const int nslots = (((ne + 3) >> 2) << 2);
    const int stride = gridDim.x * 256;

    for (int t = blockIdx.x * 256 + threadIdx.x; t < nslots; t += stride) {
        const int p  = t >> 2;
        const int q  = t & 3;
        const int e0 = p * 4;

        uint2 sd[4];
        const uint4 i0 = __ldg(reinterpret_cast<const uint4*>(esd + e0));
        sd[0] = make_uint2(i0.x, i0.y);
        sd[1] = make_uint2(i0.z, i0.w);
        if (e0 + 2 < ne) {
            const uint4 i1 = __ldg(reinterpret_cast<const uint4*>(esd + e0 + 2));
            sd[2] = make_uint2(i1.x, i1.y);
            sd[3] = make_uint2(i1.z, i1.w);
        } else {
            sd[2] = sd[0]; sd[3] = sd[0];
        }

        const int nv = min(4, ne - e0);
        uint4 v[4];
        #pragma unroll
        for (int j = 0; j < 4; j++) {
            const int e = e0 + j;
            const int r = (e >= o1) + (e >= o2) + (e >= o3);
            if (j < nv)
                v[j] = *reinterpret_cast<const uint4*>(
                    xt + (((size_t)r * nnodes + sd[j].x) << 5) + q * 8);
        }

        #pragma unroll
        for (int j = 0; j < 4; j++) {
            if (j < nv) {
                __half* ap = agg + ((size_t)sd[j].y << 5) + q * 8;
                asm volatile("red.global.add.noftz.v4.f16x2 [%0], {%1, %2, %3, %4};"
                             :: "l"(ap), "r"(v[j].x), "r"(v[j].y), "r"(v[j].z), "r"(v[j].w)
                             : "memory");
            }
        }
    }
}

// ---------------------------------------------------------------------------
// Tensor-core transform; rel-major coalesced epilogue.
// Layer 1 (!PRE_ACT): piggybacks (a) zeroing of agg1, (b) the rel histogram
// (ne/4 edges read as uint4, warp-aggregated smem counts, flushed between
// existing syncs; last-finishing block computes offsets + cursors).
// Layer 2: zeroes agg2 only.
// ---------------------------------------------------------------------------
template<bool PRE_ACT>
__global__ void __launch_bounds__(256) transform_k(
    const void* __restrict__ xin_, const float* __restrict__ W,
    const float* __restrict__ b, __half* __restrict__ xt,
    __half* __restrict__ zbuf, const int* __restrict__ et,
    int nnodes, int ne)
{
    __shared__ __align__(16) unsigned char sm[TN * ST_STRIDE * 2]; // 34816 B
    __shared__ int hh[4];
    __half* xh    = reinterpret_cast<__half*>(sm);
    __half* wh    = reinterpret_cast<__half*>(sm + 10240);
    __half* stage = reinterpret_cast<__half*>(sm);

    const int tid  = threadIdx.x;
    const int base = blockIdx.x * TN;
    const int gtid = blockIdx.x * 256 + tid;

    if (!PRE_ACT && tid < 4) hh[tid] = 0;

    {   // zero one agg buffer: nnodes*4 uint4, grid has nnodes*2 threads.
        uint4* a = reinterpret_cast<uint4*>(zbuf);
        const uint4 zz = make_uint4(0u, 0u, 0u, 0u);
        a[gtid] = zz;
        a[gtid + nnodes * 2] = zz;
    }

    // W smem: wh[d][r*32+o] = half(W[r][d][o]).
    for (int f = tid; f < 1024; f += 256) {
        const float4 v = reinterpret_cast<const float4*>(W)[f];
        const int r = f >> 8, d = (f >> 3) & 31, o4 = f & 7;
        __half* p = &wh[d * WH_STRIDE + r * 32 + o4 * 4];
        p[0] = __float2half_rn(v.x); p[1] = __float2half_rn(v.y);
        p[2] = __float2half_rn(v.z); p[3] = __float2half_rn(v.w);
    }

    // x tile.
    if (PRE_ACT) {
        const __half* xin = reinterpret_cast<const __half*>(xin_);
        for (int f = tid; f < TN * 4; f += 256) {
            const int i = f >> 2, kq = f & 3;
            const uint4 pk = *reinterpret_cast<const uint4*>(
                xin + (size_t)(base + i) * N_FEAT + kq * 8);
            const __half2* hp = reinterpret_cast<const __half2*>(&pk);
            const float4 b0 = __ldg(reinterpret_cast<const float4*>(b + kq * 8));
            const float4 b1 = __ldg(reinterpret_cast<const float4*>(b + kq * 8 + 4));
            const float bb[8] = {b0.x, b0.y, b0.z, b0.w, b1.x, b1.y, b1.z, b1.w};
            __half* d = &xh[i * XH_STRIDE + kq * 8];
            #pragma unroll
            for (int j = 0; j < 4; j++) {
                float2 fv = __half22float2(hp[j]);
                fv.x = fmaxf(fv.x + bb[j * 2 + 0], 0.f);
                fv.y = fmaxf(fv.y + bb[j * 2 + 1], 0.f);
                *reinterpret_cast<__half2*>(d + j * 2) = __floats2half2_rn(fv.x, fv.y);
            }
        }
    } else {
        const float4* xin4 = reinterpret_cast<const float4*>(
            reinterpret_cast<const float*>(xin_) + (size_t)base * N_FEAT);
        for (int f = tid; f < TN * 8; f += 256) {
            const float4 v = xin4[f];
            const int i = f >> 3, kq = f & 7;
            __half* d = &xh[i * XH_STRIDE + kq * 4];
            *reinterpret_cast<__half2*>(d)     = __floats2half2_rn(v.x, v.y);
            *reinterpret_cast<__half2*>(d + 2) = __floats2half2_rn(v.z, v.w);
        }
    }
    __syncthreads();   // (sync #1) tile ready; hh initialized

    // Fused histogram (layer 1): 4 edges per thread, warp-aggregated.
    if (!PRE_ACT) {
        const int e0 = gtid * 4;
        if (e0 < ne) {
            const uint4 ev = __ldg(reinterpret_cast<const uint4*>(et + e0));
            const int rr[4] = {(int)ev.x, (int)ev.y, (int)ev.z, (int)ev.w};
            const int nv = min(4, ne - e0);
            #pragma unroll
            for (int j = 0; j < 4; j++) {
                if (j < nv) {
                    const unsigned int mask = __match_any_sync(__activemask(), rr[j]);
                    const unsigned int lt   = (1u << (tid & 31)) - 1u;
                    if ((mask & lt) == 0u) atomicAdd(&hh[rr[j]], __popc(mask));
                }
            }
        }
    }

    const int w    = tid >> 5;
    const int lane = tid & 31;
    const int m0   = w * 16;

    uint32_t a[2][4];
    #pragma unroll
    for (int s = 0; s < 2; s++) {
        const int row = m0 + (lane & 15);
        const int col = s * 16 + ((lane >> 4) << 3);
        const uint32_t addr =
            (uint32_t)__cvta_generic_to_shared(&xh[row * XH_STRIDE + col]);
        asm volatile("ldmatrix.sync.aligned.m8n8.x4.shared.b16 {%0,%1,%2,%3}, [%4];"
                     : "=r"(a[s][0]), "=r"(a[s][1]), "=r"(a[s][2]), "=r"(a[s][3])
                     : "r"(addr));
    }

    float acc[16][4];
    #pragma unroll
    for (int j = 0; j < 16; j++)
        #pragma unroll
        for (int q = 0; q < 4; q++) acc[j][q] = 0.f;

    #pragma unroll
    for (int j = 0; j < 16; j++) {
        #pragma unroll
        for (int s = 0; s < 2; s++) {
            const int krow = s * 16 + (lane & 15);
            const uint32_t baddr =
                (uint32_t)__cvta_generic_to_shared(&wh[krow * WH_STRIDE + j * 8]);
            uint32_t b0, b1;
            asm volatile("ldmatrix.sync.aligned.m8n8.x2.trans.shared.b16 {%0,%1}, [%2];"
                         : "=r"(b0), "=r"(b1) : "r"(baddr));
            asm volatile(
                "mma.sync.aligned.m16n8k16.row.col.f32.f16.f16.f32 "
                "{%0,%1,%2,%3}, {%4,%5,%6,%7}, {%8,%9}, {%0,%1,%2,%3};"
                : "+f"(acc[j][0]), "+f"(acc[j][1]), "+f"(acc[j][2]), "+f"(acc[j][3])
                : "r"(a[s][0]), "r"(a[s][1]), "r"(a[s][2]), "r"(a[s][3]),
                  "r"(b0), "r"(b1));
        }
    }
    __syncthreads();   // (sync #2) xh/wh dead; hh adds complete

    // Flush block histogram to global (layer 1).
    if (!PRE_ACT && tid < 4 && hh[tid])
        atomicAdd(&g_cnt4[tid], hh[tid]);

    const int g  = lane >> 2;
    const int t4 = lane & 3;
    #pragma unroll
    for (int j = 0; j < 16; j++) {
        *reinterpret_cast<__half2*>(&stage[(m0 + g) * ST_STRIDE + j * 8 + t4 * 2]) =
            __floats2half2_rn(acc[j][0], acc[j][1]);
        *reinterpret_cast<__half2*>(&stage[(m0 + g + 8) * ST_STRIDE + j * 8 + t4 * 2]) =
            __floats2half2_rn(acc[j][2], acc[j][3]);
    }
    __syncthreads();   // (sync #3) staging ready; flush done block-wide

    // Last-finishing block computes offsets + cursors (layer 1).
    if (!PRE_ACT && tid == 0) {
        __threadfence();
        const unsigned int t = atomicAdd(&g_done, 1u);
        if (t == gridDim.x - 1) {
            int o = 0;
            #pragma unroll
            for (int r = 0; r < 4; r++) {
                g_off[r] = o; g_cursor[r] = o; o += g_cnt4[r];
            }
            g_off[4] = o;
            g_done = 0u;
        }
    }

    // Coalesced rel-major store.
    for (int f = tid; f < TN * 16; f += 256) {
        const int rel = f >> 9, row = (f >> 2) & 127, c4 = f & 3;
        const uint4 v = *reinterpret_cast<const uint4*>(
            &stage[row * ST_STRIDE + (rel * 4 + c4) * 8]);
        *reinterpret_cast<uint4*>(
            xt + (((size_t)rel * nnodes + base + row) << 5) + c4 * 8) = v;
    }
}

// ---------------------------------------------------------------------------
// Pool: out[g][c] = mean_{i<32} relu(agg2[g*32+i][c] + b[c]).
// ---------------------------------------------------------------------------
__global__ void __launch_bounds__(256) pool_k(
    const __half* __restrict__ agg, const float* __restrict__ b,
    float* __restrict__ out, int nnodes)
{
    const int t = blockIdx.x * blockDim.x + threadIdx.x;
    if (t >= nnodes) return;
    const int c = t & 31;
    const int g = t >> 5;
    const float bc = __ldg(b + c);
    const __half* p = agg + (size_t)g * 32 * N_FEAT + c;
    float s = 0.f;
    #pragma unroll
    for (int i = 0; i < 32; i++)
        s += fmaxf(__half2float(p[i * N_FEAT]) + bc, 0.f);
    out[t] = s * (1.0f / 32.0f);
}

// ---------------------------------------------------------------------------
// Launch order: 0 zc, 1 tf<0>(+hist+zero agg1), 2 reorder,
// 3 scatter1 (ncu capture slot), 4 tf<1>(+zero agg2), 5 scatter2, 6 pool.
// ---------------------------------------------------------------------------
extern "C" void kernel_launch(void* const* d_in, const int* in_sizes, int n_in,
                              void* d_out, int out_size)
{
    const float* x   = (const float*)d_in[0];
    const int*   src = (const int*)  d_in[1];
    const int*   dst = (const int*)  d_in[2];
    const int*   et  = (const int*)  d_in[3];
    const float* W   = (const float*)d_in[4];
    const float* b   = (const float*)d_in[5];

    const int nnodes = in_sizes[0] / N_FEAT;
    const int nedges = in_sizes[1];

    __half *xt, *agg1, *agg2; uint2 *esd;
    cudaGetSymbolAddress((void**)&xt,   g_xt);
    cudaGetSymbolAddress((void**)&agg1, g_agg1);
    cudaGetSymbolAddress((void**)&agg2, g_agg2);
    cudaGetSymbolAddress((void**)&esd,  g_esd);

    const int tf_blocks = nnodes / TN;
    const int eb_blocks = (nedges + 255) / 256;
    const int sc_blocks = 148 * 7;   // persistent grid-stride

    zc_k<<<1, 32>>>();
    transform_k<false><<<tf_blocks, 256>>>(x, W, b, xt, agg1, et, nnodes, nedges);
    reorder_k<<<eb_blocks, 256>>>(src, dst, et, esd, nedges);
    scatter_k<<<sc_blocks, 256>>>(xt, esd, agg1, nedges, nnodes);
    transform_k<true><<<tf_blocks, 256>>>(agg1, W, b, xt, agg2, nullptr, nnodes, nedges);
    scatter_k<<<sc_blocks, 256>>>(xt, esd, agg2, nedges, nnodes);
    pool_k<<<(nnodes + 255) / 256, 256>>>(agg2, b, (float*)d_out, nnodes);
    (void)n_in; (void)out_size;
}

// round 15
// speedup vs baseline: 1.1091x; 1.1091x over previous
#include <cuda_runtime.h>
#include <cuda_fp16.h>
#include <cstdint>

#define N_FEAT 32
#define MAX_NODES 524288
#define MAX_EDGES 4194304
#define TN 128

#define XH_STRIDE 40
#define WH_STRIDE 136
#define ST_STRIDE 136

// Scratch. xt REL-MAJOR: xt[rel][node][32] fp16 (4 x 32 MB).
__device__ __half g_xt[(size_t)4 * MAX_NODES * N_FEAT];
__device__ __half g_agg1[(size_t)MAX_NODES * N_FEAT];
__device__ __half g_agg2[(size_t)MAX_NODES * N_FEAT];
__device__ uint2  g_esd[MAX_EDGES];          // (src,dst) binned by rel
__device__ int g_cnt4[4];
__device__ int g_off[5];
__device__ int g_cursor[4];
__device__ unsigned int g_done;

// ---------------------------------------------------------------------------
// Rel histogram, warp-aggregated. Last block computes offsets + cursors.
// Counters zeroed by tf<false>.
// ---------------------------------------------------------------------------
__global__ void __launch_bounds__(256) hist_k(const int* __restrict__ et, int ne)
{
    __shared__ int h[4];
    if (threadIdx.x < 4) h[threadIdx.x] = 0;
    __syncthreads();

    const int e = blockIdx.x * 256 + threadIdx.x;
    if (e < ne) {
        const int r = __ldg(et + e);
        const unsigned int mask = __match_any_sync(__activemask(), r);
        const unsigned int lt   = (1u << (threadIdx.x & 31)) - 1u;
        if ((mask & lt) == 0u)
            atomicAdd(&h[r], __popc(mask));
    }
    __syncthreads();

    if (threadIdx.x < 4 && h[threadIdx.x])
        atomicAdd(&g_cnt4[threadIdx.x], h[threadIdx.x]);
    __threadfence();
    __syncthreads();

    if (threadIdx.x == 0) {
        const unsigned int t = atomicAdd(&g_done, 1u);
        if (t == gridDim.x - 1) {
            int o = 0;
            #pragma unroll
            for (int r = 0; r < 4; r++) {
                g_off[r] = o; g_cursor[r] = o; o += g_cnt4[r];
            }
            g_off[4] = o;
            g_done = 0;
        }
    }
}

// ---------------------------------------------------------------------------
// Reorder into rel bins; warp-aggregated ranking, block-aggregated cursors.
// ---------------------------------------------------------------------------
__global__ void __launch_bounds__(256) reorder_k(
    const int* __restrict__ src, const int* __restrict__ dst,
    const int* __restrict__ et, uint2* __restrict__ esd, int ne)
{
    __shared__ int h[4];
    __shared__ int base[4];
    if (threadIdx.x < 4) h[threadIdx.x] = 0;
    __syncthreads();

    const int e = blockIdx.x * 256 + threadIdx.x;
    int r = 0, pos_local = 0;
    uint2 sd = make_uint2(0u, 0u);
    const bool valid = (e < ne);
    if (valid) {
        r = __ldg(et + e);
        sd.x = (unsigned int)__ldg(src + e);
        sd.y = (unsigned int)__ldg(dst + e);
        const unsigned int mask = __match_any_sync(__activemask(), r);
        const unsigned int lt   = (1u << (threadIdx.x & 31)) - 1u;
        const int rank = __popc(mask & lt);
        int wbase = 0;
        if (rank == 0) wbase = atomicAdd(&h[r], __popc(mask));
        const int leader = __ffs(mask) - 1;
        wbase = __shfl_sync(0xffffffffu, wbase, leader);
        pos_local = wbase + rank;
    }
    __syncthreads();
    if (threadIdx.x < 4)
        base[threadIdx.x] = atomicAdd(&g_cursor[threadIdx.x], h[threadIdx.x]);
    __syncthreads();
    if (valid) esd[base[r] + pos_local] = sd;
}

// ---------------------------------------------------------------------------
// Binned scatter (one-shot, R13 structure): 4 edges per thread, 4 lanes per
// edge. __launch_bounds__(256, 8) caps regs at 32 -> 8 blocks/SM ceiling.
// ---------------------------------------------------------------------------
__global__ void __launch_bounds__(256, 8) scatter_k(
    const __half* __restrict__ xt, const uint2* __restrict__ esd,
    __half* __restrict__ agg, int ne, int nnodes)
{
    const int t = blockIdx.x * 256 + threadIdx.x;
    const int p = t >> 2;            // group of 4 edges
    const int q = t & 3;
    const int e0 = p * 4;
    if (e0 >= ne) return;

    const int o1 = __ldg(&g_off[1]), o2 = __ldg(&g_off[2]), o3 = __ldg(&g_off[3]);

    uint2 sd[4];
    {
        const uint4 i0 = __ldg(reinterpret_cast<const uint4*>(esd + e0));
        sd[0] = make_uint2(i0.x, i0.y);
        sd[1] = make_uint2(i0.z, i0.w);
        if (e0 + 2 < ne) {
            const uint4 i1 = __ldg(reinterpret_cast<const uint4*>(esd + e0 + 2));
            sd[2] = make_uint2(i1.x, i1.y);
            sd[3] = make_uint2(i1.z, i1.w);
        } else {
            sd[2] = sd[0]; sd[3] = sd[0];
        }
    }

    const int nv = min(4, ne - e0);
    uint4 v[4];
    #pragma unroll
    for (int j = 0; j < 4; j++) {
        const int e = e0 + j;
        const int r = (e >= o1) + (e >= o2) + (e >= o3);
        if (j < nv)
            v[j] = *reinterpret_cast<const uint4*>(
                xt + (((size_t)r * nnodes + sd[j].x) << 5) + q * 8);
    }

    #pragma unroll
    for (int j = 0; j < 4; j++) {
        if (j < nv) {
            __half* ap = agg + ((size_t)sd[j].y << 5) + q * 8;
            asm volatile("red.global.add.noftz.v4.f16x2 [%0], {%1, %2, %3, %4};"
                         :: "l"(ap), "r"(v[j].x), "r"(v[j].y), "r"(v[j].z), "r"(v[j].w)
                         : "memory");
        }
    }
}

// ---------------------------------------------------------------------------
// Tensor-core transform; rel-major coalesced epilogue. zbuf: agg buffer to
// zero (agg1 in layer 1, agg2 in layer 2); layer 1 also resets counters.
// ---------------------------------------------------------------------------
template<bool PRE_ACT>
__global__ void __launch_bounds__(256) transform_k(
    const void* __restrict__ xin_, const float* __restrict__ W,
    const float* __restrict__ b, __half* __restrict__ xt,
    __half* __restrict__ zbuf, int nnodes)
{
    __shared__ __align__(16) unsigned char sm[TN * ST_STRIDE * 2]; // 34816 B
    __half* xh    = reinterpret_cast<__half*>(sm);
    __half* wh    = reinterpret_cast<__half*>(sm + 10240);
    __half* stage = reinterpret_cast<__half*>(sm);

    const int tid  = threadIdx.x;
    const int base = blockIdx.x * TN;

    {   // zero one agg buffer: nnodes*4 uint4, grid has nnodes*2 threads.
        const int gtid = blockIdx.x * 256 + tid;
        uint4* a = reinterpret_cast<uint4*>(zbuf);
        const uint4 zz = make_uint4(0u, 0u, 0u, 0u);
        a[gtid] = zz;
        a[gtid + nnodes * 2] = zz;
        if (!PRE_ACT && gtid == 0) {
            g_cnt4[0] = g_cnt4[1] = g_cnt4[2] = g_cnt4[3] = 0;
            g_done = 0u;
        }
    }

    // W smem: wh[d][r*32+o] = half(W[r][d][o]).
    for (int f = tid; f < 1024; f += 256) {
        const float4 v = reinterpret_cast<const float4*>(W)[f];
        const int r = f >> 8, d = (f >> 3) & 31, o4 = f & 7;
        __half* p = &wh[d * WH_STRIDE + r * 32 + o4 * 4];
        p[0] = __float2half_rn(v.x); p[1] = __float2half_rn(v.y);
        p[2] = __float2half_rn(v.z); p[3] = __float2half_rn(v.w);
    }

    // x tile.
    if (PRE_ACT) {
        const __half* xin = reinterpret_cast<const __half*>(xin_);
        for (int f = tid; f < TN * 4; f += 256) {
            const int i = f >> 2, kq = f & 3;
            const uint4 pk = *reinterpret_cast<const uint4*>(
                xin + (size_t)(base + i) * N_FEAT + kq * 8);
            const __half2* hp = reinterpret_cast<const __half2*>(&pk);
            const float4 b0 = __ldg(reinterpret_cast<const float4*>(b + kq * 8));
            const float4 b1 = __ldg(reinterpret_cast<const float4*>(b + kq * 8 + 4));
            const float bb[8] = {b0.x, b0.y, b0.z, b0.w, b1.x, b1.y, b1.z, b1.w};
            __half* d = &xh[i * XH_STRIDE + kq * 8];
            #pragma unroll
            for (int j = 0; j < 4; j++) {
                float2 fv = __half22float2(hp[j]);
                fv.x = fmaxf(fv.x + bb[j * 2 + 0], 0.f);
                fv.y = fmaxf(fv.y + bb[j * 2 + 1], 0.f);
                *reinterpret_cast<__half2*>(d + j * 2) = __floats2half2_rn(fv.x, fv.y);
            }
        }
    } else {
        const float4* xin4 = reinterpret_cast<const float4*>(
            reinterpret_cast<const float*>(xin_) + (size_t)base * N_FEAT);
        for (int f = tid; f < TN * 8; f += 256) {
            const float4 v = xin4[f];
            const int i = f >> 3, kq = f & 7;
            __half* d = &xh[i * XH_STRIDE + kq * 4];
            *reinterpret_cast<__half2*>(d)     = __floats2half2_rn(v.x, v.y);
            *reinterpret_cast<__half2*>(d + 2) = __floats2half2_rn(v.z, v.w);
        }
    }
    __syncthreads();

    const int w    = tid >> 5;
    const int lane = tid & 31;
    const int m0   = w * 16;

    uint32_t a[2][4];
    #pragma unroll
    for (int s = 0; s < 2; s++) {
        const int row = m0 + (lane & 15);
        const int col = s * 16 + ((lane >> 4) << 3);
        const uint32_t addr =
            (uint32_t)__cvta_generic_to_shared(&xh[row * XH_STRIDE + col]);
        asm volatile("ldmatrix.sync.aligned.m8n8.x4.shared.b16 {%0,%1,%2,%3}, [%4];"
                     : "=r"(a[s][0]), "=r"(a[s][1]), "=r"(a[s][2]), "=r"(a[s][3])
                     : "r"(addr));
    }

    float acc[16][4];
    #pragma unroll
    for (int j = 0; j < 16; j++)
        #pragma unroll
        for (int q = 0; q < 4; q++) acc[j][q] = 0.f;

    #pragma unroll
    for (int j = 0; j < 16; j++) {
        #pragma unroll
        for (int s = 0; s < 2; s++) {
            const int krow = s * 16 + (lane & 15);
            const uint32_t baddr =
                (uint32_t)__cvta_generic_to_shared(&wh[krow * WH_STRIDE + j * 8]);
            uint32_t b0, b1;
            asm volatile("ldmatrix.sync.aligned.m8n8.x2.trans.shared.b16 {%0,%1}, [%2];"
                         : "=r"(b0), "=r"(b1) : "r"(baddr));
            asm volatile(
                "mma.sync.aligned.m16n8k16.row.col.f32.f16.f16.f32 "
                "{%0,%1,%2,%3}, {%4,%5,%6,%7}, {%8,%9}, {%0,%1,%2,%3};"
                : "+f"(acc[j][0]), "+f"(acc[j][1]), "+f"(acc[j][2]), "+f"(acc[j][3])
                : "r"(a[s][0]), "r"(a[s][1]), "r"(a[s][2]), "r"(a[s][3]),
                  "r"(b0), "r"(b1));
        }
    }
    __syncthreads();

    const int g  = lane >> 2;
    const int t4 = lane & 3;
    #pragma unroll
    for (int j = 0; j < 16; j++) {
        *reinterpret_cast<__half2*>(&stage[(m0 + g) * ST_STRIDE + j * 8 + t4 * 2]) =
            __floats2half2_rn(acc[j][0], acc[j][1]);
        *reinterpret_cast<__half2*>(&stage[(m0 + g + 8) * ST_STRIDE + j * 8 + t4 * 2]) =
            __floats2half2_rn(acc[j][2], acc[j][3]);
    }
    __syncthreads();

    // Coalesced rel-major store.
    for (int f = tid; f < TN * 16; f += 256) {
        const int rel = f >> 9, row = (f >> 2) & 127, c4 = f & 3;
        const uint4 v = *reinterpret_cast<const uint4*>(
            &stage[row * ST_STRIDE + (rel * 4 + c4) * 8]);
        *reinterpret_cast<uint4*>(
            xt + (((size_t)rel * nnodes + base + row) << 5) + c4 * 8) = v;
    }
}

// ---------------------------------------------------------------------------
// Pool: out[g][c] = mean_{i<32} relu(agg2[g*32+i][c] + b[c]).
// ---------------------------------------------------------------------------
__global__ void __launch_bounds__(256) pool_k(
    const __half* __restrict__ agg, const float* __restrict__ b,
    float* __restrict__ out, int nnodes)
{
    const int t = blockIdx.x * blockDim.x + threadIdx.x;
    if (t >= nnodes) return;
    const int c = t & 31;
    const int g = t >> 5;
    const float bc = __ldg(b + c);
    const __half* p = agg + (size_t)g * 32 * N_FEAT + c;
    float s = 0.f;
    #pragma unroll
    for (int i = 0; i < 32; i++)
        s += fmaxf(__half2float(p[i * N_FEAT]) + bc, 0.f);
    out[t] = s * (1.0f / 32.0f);
}

// ---------------------------------------------------------------------------
// Launch order: 0 tf<0>(+zero agg1+counters), 1 hist, 2 reorder,
// 3 scatter1 (ncu capture slot), 4 tf<1>(+zero agg2), 5 scatter2, 6 pool.
// ---------------------------------------------------------------------------
extern "C" void kernel_launch(void* const* d_in, const int* in_sizes, int n_in,
                              void* d_out, int out_size)
{
    const float* x   = (const float*)d_in[0];
    const int*   src = (const int*)  d_in[1];
    const int*   dst = (const int*)  d_in[2];
    const int*   et  = (const int*)  d_in[3];
    const float* W   = (const float*)d_in[4];
    const float* b   = (const float*)d_in[5];

    const int nnodes = in_sizes[0] / N_FEAT;
    const int nedges = in_sizes[1];

    __half *xt, *agg1, *agg2; uint2 *esd;
    cudaGetSymbolAddress((void**)&xt,   g_xt);
    cudaGetSymbolAddress((void**)&agg1, g_agg1);
    cudaGetSymbolAddress((void**)&agg2, g_agg2);
    cudaGetSymbolAddress((void**)&esd,  g_esd);

    const int tf_blocks = nnodes / TN;
    const int eb_blocks = (nedges + 255) / 256;
    const int sc_blocks = (nedges + 255) / 256;   // 4 edges/thread, 4 lanes

    transform_k<false><<<tf_blocks, 256>>>(x, W, b, xt, agg1, nnodes);
    hist_k<<<eb_blocks, 256>>>(et, nedges);
    reorder_k<<<eb_blocks, 256>>>(src, dst, et, esd, nedges);
    scatter_k<<<sc_blocks, 256>>>(xt, esd, agg1, nedges, nnodes);
    transform_k<true><<<tf_blocks, 256>>>(agg1, W, b, xt, agg2, nnodes);
    scatter_k<<<sc_blocks, 256>>>(xt, esd, agg2, nedges, nnodes);
    pool_k<<<(nnodes + 255) / 256, 256>>>(agg2, b, (float*)d_out, nnodes);
    (void)n_in; (void)out_size;
}